// round 15
// baseline (speedup 1.0000x reference)
#include <cuda_runtime.h>
#include <cuda.h>
#include <cuda_bf16.h>
#include <cstdint>
#include <math.h>

#define NB    2048
#define DD    16
#define EE    256
#define HH    768
#define G3    2304
#define TT    8
#define NPRED 12
#define SCALEF 4.0f

#if defined(__CUDA_ARCH_FEAT_SM103_ALL) || defined(__CUDA_ARCH_FEAT_SM100_ALL) || \
    (defined(__CUDA_ARCH_SPECIFIC__) && (__CUDA_ARCH_SPECIFIC__ >= 1000))
#define HAS_TCG 1
#else
#define HAS_TCG 0
#endif

// ---------------- device scratch ----------------
__device__ __align__(256) __nv_bfloat16 g_Bh1[G3*HH];   // gate-permuted Whh hi/lo
__device__ __align__(256) __nv_bfloat16 g_Bl1[G3*HH];
__device__ __align__(256) __nv_bfloat16 g_Bh2[G3*HH];
__device__ __align__(256) __nv_bfloat16 g_Bl2[G3*HH];
__device__ __align__(256) __nv_bfloat16 g_Bhd[G3*HH];
__device__ __align__(256) __nv_bfloat16 g_Bld[G3*HH];
__device__ __align__(256) __nv_bfloat16 g_Bh2x[G3*HH];
__device__ __align__(256) __nv_bfloat16 g_Bl2x[G3*HH];
__device__ __align__(256) __nv_bfloat16 g_MeA1[G3*64];  // ext B: [Mhi|Mlo|Mhi|0] per row
__device__ __align__(256) __nv_bfloat16 g_MeA2[G3*64];
__device__ __align__(256) __nv_bfloat16 g_MeAd[G3*64];
__device__ __align__(256) float g_bv1[G3];
__device__ __align__(256) float g_bh1[G3];
__device__ __align__(256) float g_bv2[G3];
__device__ __align__(256) float g_bh2[G3];
__device__ __align__(256) float g_bvd[G3];
__device__ __align__(256) float g_bhd[G3];
__device__ __align__(256) __nv_bfloat16 g_Ah[NB*HH];
__device__ __align__(256) __nv_bfloat16 g_Al[NB*HH];
__device__ __align__(256) float g_C2T[G3*NB];           // permuted, transposed [p][row]
__device__ __align__(256) float g_h[NB*HH];

// ---------------- helpers ----------------
__device__ __forceinline__ uint32_t smem_u32(const void* p) {
    uint32_t a;
    asm("{ .reg .u64 t; cvta.to.shared.u64 t, %1; cvt.u32.u64 %0, t; }" : "=r"(a) : "l"(p));
    return a;
}
__device__ __forceinline__ uint32_t elect_one() {
    uint32_t pred;
    asm volatile("{\n\t.reg .pred p;\n\telect.sync _|p, 0xFFFFFFFF;\n\t"
                 "selp.b32 %0, 1, 0, p;\n\t}" : "=r"(pred));
    return pred;
}
__device__ __forceinline__ uint32_t ctarank() {
    uint32_t r;
    asm("mov.u32 %0, %%cluster_ctarank;" : "=r"(r));
    return r;
}
__device__ __forceinline__ void mbar_init(uint32_t m, uint32_t c) {
    asm volatile("mbarrier.init.shared.b64 [%0], %1;" :: "r"(m), "r"(c) : "memory");
}
__device__ __forceinline__ void mbar_inval(uint32_t m) {
    asm volatile("mbarrier.inval.shared.b64 [%0];" :: "r"(m) : "memory");
}
__device__ __forceinline__ void mbar_wait(uint32_t m, uint32_t par) {
    uint32_t done;
    asm volatile("{\n\t.reg .pred p;\n\t"
        "mbarrier.try_wait.parity.acquire.cta.shared::cta.b64 p, [%1], %2;\n\t"
        "selp.b32 %0, 1, 0, p;\n\t}" : "=r"(done) : "r"(m), "r"(par) : "memory");
    while (!done) {
        asm volatile("{\n\t.reg .pred p;\n\t"
            "mbarrier.try_wait.parity.acquire.cta.shared::cta.b64 p, [%1], %2, 0x989680;\n\t"
            "selp.b32 %0, 1, 0, p;\n\t}" : "=r"(done) : "r"(m), "r"(par) : "memory");
    }
}
#define CLUSTER_SYNC() do { \
    asm volatile("barrier.cluster.arrive.aligned;" ::: "memory"); \
    asm volatile("barrier.cluster.wait.aligned;" ::: "memory"); \
} while (0)
#define FENCE_ASYNC_SHARED() asm volatile("fence.proxy.async.shared::cta;" ::: "memory")

__device__ __forceinline__ uint32_t swz128(uint32_t off) { return off ^ ((off >> 3) & 0x70); }
__device__ __forceinline__ uint32_t pack2(__nv_bfloat16 a, __nv_bfloat16 b) {
    __nv_bfloat162 t; t.x = a; t.y = b; return *reinterpret_cast<uint32_t*>(&t);
}
__device__ __forceinline__ int gatemap(int p) {   // permuted row -> original row
    int blk = p / 384, rem = p % 384;
    return (rem >> 7) * HH + blk * 128 + (rem & 127);
}

#if HAS_TCG
#define TC_ALLOC_CG2(s, n)   asm volatile("tcgen05.alloc.cta_group::2.sync.aligned.shared::cta.b32 [%0], %1;" :: "r"(s), "r"((uint32_t)(n)) : "memory")
#define TC_DEALLOC_CG2(t, n) asm volatile("tcgen05.dealloc.cta_group::2.sync.aligned.b32 %0, %1;" :: "r"(t), "r"((uint32_t)(n)))
#define TC_RELINQUISH_CG2()  asm volatile("tcgen05.relinquish_alloc_permit.cta_group::2.sync.aligned;")
#define TC_COMMIT_MC2(m) \
    asm volatile("tcgen05.commit.cta_group::2.mbarrier::arrive::one.shared::cluster.multicast::cluster.b64 [%0], %1;" \
        :: "r"(m), "h"((uint16_t)0x3) : "memory")
#define TC_FENCE_AFTER()  asm volatile("tcgen05.fence::after_thread_sync;" ::: "memory")
#define TC_FENCE_BEFORE() asm volatile("tcgen05.fence::before_thread_sync;" ::: "memory")
#define TC_WAIT_LD()      asm volatile("tcgen05.wait::ld.sync.aligned;" ::: "memory")

#define TC_LD_X16(r, addr) \
    asm volatile("tcgen05.ld.sync.aligned.32x32b.x16.b32 " \
        "{%0, %1, %2, %3, %4, %5, %6, %7, %8, %9, %10, %11, %12, %13, %14, %15}, [%16];" \
        : "=r"((r)[0]),  "=r"((r)[1]),  "=r"((r)[2]),  "=r"((r)[3]), \
          "=r"((r)[4]),  "=r"((r)[5]),  "=r"((r)[6]),  "=r"((r)[7]), \
          "=r"((r)[8]),  "=r"((r)[9]),  "=r"((r)[10]), "=r"((r)[11]), \
          "=r"((r)[12]), "=r"((r)[13]), "=r"((r)[14]), "=r"((r)[15]) \
        : "r"(addr))

__device__ __forceinline__ void mma_cg2(uint32_t d, uint64_t ad, uint64_t bd,
                                        uint32_t idesc, uint32_t en) {
    asm volatile("{\n\t.reg .pred p;\n\tsetp.ne.u32 p, %5, 0;\n\t"
        "tcgen05.mma.cta_group::2.kind::f16 [%0], %1, %2, %3, "
        "{%4, %4, %4, %4, %4, %4, %4, %4}, p;\n\t}"
        :: "r"(d), "l"(ad), "l"(bd), "r"(idesc), "r"(0u), "r"(en) : "memory");
}
// dtype=F32, a/b=BF16, N=128 (N/8=16), M=256 (M/16=16)
#define ID128 ((1u<<4) | (1u<<7) | (1u<<10) | (16u<<17) | (16u<<24))

__device__ __forceinline__ uint64_t dsw128(uint32_t addr) {
    const uint64_t base =
        (uint64_t(2) << 61) | (uint64_t(1) << 46) | (uint64_t(64) << 32) | (uint64_t(1) << 16);
    return base | ((uint64_t)(addr >> 4) & 0x3FFF);
}

#define MBAR_EXPECT_TX(m, bytes) \
    asm volatile("mbarrier.arrive.expect_tx.shared.b64 _, [%0], %1;" \
                 :: "r"(m), "r"((uint32_t)(bytes)) : "memory")
#define TMA_LD_2D_CG2(dst, map, x, y, mbar) \
    asm volatile("{\n\t.reg .b32 lb;\n\t" \
        "and.b32 lb, %4, 0xFEFFFFFF;\n\t" \
        "cp.async.bulk.tensor.2d.cta_group::2.shared::cluster.global.tile.mbarrier::complete_tx::bytes " \
        "[%0], [%1, {%2, %3}], [lb];\n\t}" \
        :: "r"(dst), "l"(map), "r"(x), "r"(y), "r"(mbar) : "memory")
#endif

// ---------------- fused cg2 GEMM + GRU step kernel ----------------
// Cluster pair: M=256 rows, hidden block nblk (128 units x 3 gates).
// TMEM: cols 0-127 r, 128-255 z, 256-383 gh_n, 384-511 gi_n.
// Per-gate cg2 N=128 MMAs; B rows per rank r, gate g: nblk*384+g*128+r*64,
// stored at local offset g*GT.
#define KC      64
#define NRING   (HH / KC)   // 12
#define ATILE   16384       // 128 rows x 128B
#define GT      8192        // 64 rows x 128B (per-gate B tile per rank)
#define BTILE   (3*GT)      // 24576
#define SLOTB   (2*ATILE + 2*BTILE)   // 81920
#define EXTOFF  (1024 + 2*SLOTB)      // 164864
#define FUSED_SMEM (EXTOFF + ATILE + BTILE + 1024)   // 206848

__global__ void __launch_bounds__(256, 1) __cluster_dims__(2, 1, 1)
gemm_gru(const __grid_constant__ CUtensorMap mAh, const __grid_constant__ CUtensorMap mAl,
         const __grid_constant__ CUtensorMap mBh, const __grid_constant__ CUtensorMap mBl,
         const __grid_constant__ CUtensorMap mMeA,
         const float* __restrict__ bvp, const float* __restrict__ bhp,
         const float* __restrict__ C2T,
         const float* __restrict__ pa, const float* __restrict__ pb,
         float* __restrict__ hbuf,
         __nv_bfloat16* __restrict__ oAh, __nv_bfloat16* __restrict__ oAl,
         float* __restrict__ c2out,
         const __nv_bfloat16* __restrict__ BhR, const __nv_bfloat16* __restrict__ BlR,
         const __nv_bfloat16* __restrict__ MeAR,
         const __nv_bfloat16* __restrict__ AhR, const __nv_bfloat16* __restrict__ AlR,
         int hasH, int useC2, int mode) {
    extern __shared__ char smem[];
    int tid = threadIdx.x, wid = tid >> 5, lane = tid & 31;
    int nblk = blockIdx.x >> 1, rowblk = blockIdx.y;
    int nring = (mode == 1) ? NRING : (hasH ? NRING : 0);
#if HAS_TCG
    uint32_t sb = smem_u32(smem);
    uint32_t rank = ctarank();
    // bars: full 16,24 ; empty 32,40 ; done 48 ; extf 56
    if (wid == 0) TC_ALLOC_CG2(sb, 512);
    if (tid == 0) {
        mbar_init(sb+16,1); mbar_init(sb+24,1);
        mbar_init(sb+32,1); mbar_init(sb+40,1);
        mbar_init(sb+48,1); mbar_init(sb+56,1);
    }
    __syncthreads();
    CLUSTER_SYNC();
    uint32_t tmem;
    asm volatile("ld.shared.b32 %0, [%1];" : "=r"(tmem) : "r"(sb));

    int arow = rowblk * 256 + rank * 128;

    // build vext in smem (mode 0): [vhi|vhi|vlo|0], 128 rows x 64 bf16, SW128
    if (mode == 0) {
        char* ve = smem + EXTOFF;
        #pragma unroll
        for (int it = 0; it < 4; it++) {
            int ss = tid + it * 256;
            int row = ss >> 3, q = ss & 7;
            uint32_t w[4];
            if (q >= 6) {
                w[0] = w[1] = w[2] = w[3] = 0u;
            } else {
                int d0 = (q & 1) * 8;
                int wantLo = (q >= 4);
                const float* par = pa + (size_t)(arow + row) * DD + d0;
                const float* pbr = pb + (size_t)(arow + row) * DD + d0;
                #pragma unroll
                for (int e2 = 0; e2 < 4; e2++) {
                    float x0 = par[2*e2]   - pbr[2*e2];
                    float x1 = par[2*e2+1] - pbr[2*e2+1];
                    __nv_bfloat16 h0 = __float2bfloat16(x0);
                    __nv_bfloat16 h1 = __float2bfloat16(x1);
                    if (!wantLo) w[e2] = pack2(h0, h1);
                    else w[e2] = pack2(__float2bfloat16(x0 - __bfloat162float(h0)),
                                       __float2bfloat16(x1 - __bfloat162float(h1)));
                }
            }
            *(uint4*)(ve + swz128(row * 128 + q * 16)) = make_uint4(w[0], w[1], w[2], w[3]);
        }
        FENCE_ASYNC_SHARED();
    }
    __syncthreads();

    if (wid == 1 && elect_one()) {
        // -------- producer --------
        if (mode == 0) {
            if (rank == 0) MBAR_EXPECT_TX(sb + 56, 2 * BTILE);
            #pragma unroll
            for (int g = 0; g < 3; g++)
                TMA_LD_2D_CG2(sb + EXTOFF + ATILE + g*GT, &mMeA, 0,
                              nblk*384 + g*128 + rank*64, sb + 56);
        }
        for (int i = 0; i < nring; i++) {
            int slot = i & 1;
            uint32_t stgu = sb + 1024 + slot * SLOTB;
            uint32_t fb = sb + 16 + 8 * slot;
            if (i >= 2) mbar_wait(sb + 32 + 8 * slot, ((i - 2) >> 1) & 1);
            if (rank == 0) MBAR_EXPECT_TX(fb, 2 * SLOTB);
            int kc0 = i * KC;
            TMA_LD_2D_CG2(stgu,         &mAh, kc0, arow, fb);
            TMA_LD_2D_CG2(stgu + ATILE, &mAl, kc0, arow, fb);
            #pragma unroll
            for (int g = 0; g < 3; g++) {
                int br = nblk*384 + g*128 + rank*64;
                TMA_LD_2D_CG2(stgu + 2*ATILE + g*GT,         &mBh, kc0, br, fb);
                TMA_LD_2D_CG2(stgu + 2*ATILE + BTILE + g*GT, &mBl, kc0, br, fb);
            }
        }
    } else if (wid == 0 && rank == 0 && elect_one()) {
        // -------- consumer (leader) --------
        if (mode == 0) {
            mbar_wait(sb + 56, 0);
            uint64_t dV = dsw128(sb + EXTOFF);
            #pragma unroll
            for (int s = 0; s < 3; s++) {   // vhi*Mhi, vhi*Mlo, vlo*Mhi
                uint64_t o = (uint64_t)(s * 2);
                #pragma unroll
                for (int g = 0; g < 3; g++) {
                    uint32_t acc = tmem + ((g == 2) ? 384 : g * 128);
                    uint64_t dM = dsw128(sb + EXTOFF + ATILE + g*GT);
                    mma_cg2(acc, dV + o, dM + o, ID128, s > 0);
                }
            }
        }
        for (int i = 0; i < nring; i++) {
            int slot = i & 1;
            uint32_t stgu = sb + 1024 + slot * SLOTB;
            mbar_wait(sb + 16 + 8 * slot, (i >> 1) & 1);
            uint64_t dAh = dsw128(stgu);
            uint64_t dAl = dsw128(stgu + ATILE);
            #pragma unroll
            for (int s = 0; s < 4; s++) {
                uint64_t o = (uint64_t)(s * 2);
                #pragma unroll
                for (int g = 0; g < 3; g++) {
                    uint32_t acc = tmem + g * 128;
                    uint64_t dBh = dsw128(stgu + 2*ATILE + g*GT);
                    uint64_t dBl = dsw128(stgu + 2*ATILE + BTILE + g*GT);
                    // init (enable=0) on first k-step:
                    //   mode 1: all gates (fresh accumulators)
                    //   mode 0: only gate 2 (col 256 = gh_n; ext wrote gi_n to 384);
                    //           gates 0/1 accumulate onto ext gi_r/gi_z
                    uint32_t en0;
                    if (i == 0 && s == 0)
                        en0 = (mode == 1) ? 0u : ((g == 2) ? 0u : 1u);
                    else
                        en0 = 1u;
                    mma_cg2(acc, dAh + o, dBh + o, ID128, en0);
                    mma_cg2(acc, dAh + o, dBl + o, ID128, 1u);
                    mma_cg2(acc, dAl + o, dBh + o, ID128, 1u);
                }
            }
            TC_COMMIT_MC2(sb + 32 + 8 * slot);
        }
        TC_COMMIT_MC2(sb + 48);   // done
    }
    if (tid == 0) mbar_wait(sb + 48, 0);
    __syncthreads();
    TC_FENCE_AFTER();

    int sub = wid & 3, half = wid >> 2;
    int rowg = rowblk * 256 + rank * 128 + sub * 32 + lane;

    if (mode == 1) {
        #pragma unroll
        for (int cb = 0; cb < 12; cb++) {
            int c0 = half * 192 + cb * 16;
            uint32_t u[16];
            TC_LD_X16(u, tmem + c0);
            TC_WAIT_LD();
            #pragma unroll
            for (int e = 0; e < 16; e++)
                c2out[(size_t)(nblk*384 + c0 + e) * NB + rowg] = __uint_as_float(u[e]);
        }
    } else {
        float* sbv = (float*)(smem + EXTOFF);
        float* sbh = (float*)(smem + EXTOFF + 1536);
        __syncthreads();
        for (int x = tid; x < 384; x += 256) {
            sbv[x] = bvp[nblk*384 + x];
            sbh[x] = bhp[nblk*384 + x];
        }
        __syncthreads();
        int u0 = half * 64;
        float* hrow = hbuf + (size_t)rowg * HH + nblk * 128;
        __nv_bfloat16* ahr = oAh + (size_t)rowg * HH + nblk * 128;
        __nv_bfloat16* alr = oAl + (size_t)rowg * HH + nblk * 128;
        #pragma unroll
        for (int eb = 0; eb < 4; eb++) {
            int c0 = u0 + eb * 16;
            uint32_t ur[16], uz[16], un[16], ui[16];
            TC_LD_X16(ur, tmem + c0);
            TC_LD_X16(uz, tmem + 128 + c0);
            TC_LD_X16(un, tmem + 256 + c0);
            TC_LD_X16(ui, tmem + 384 + c0);
            TC_WAIT_LD();
            float hv[16];
            if (hasH) {
                #pragma unroll
                for (int q = 0; q < 4; q++)
                    *(float4*)(hv + q*4) = *(const float4*)(hrow + c0 + q*4);
            } else {
                #pragma unroll
                for (int e = 0; e < 16; e++) hv[e] = 0.0f;
            }
            #pragma unroll
            for (int e = 0; e < 16; e++) {
                int u = c0 + e;
                float rpre = __uint_as_float(ur[e]) + sbv[u]       + sbh[u];
                float zpre = __uint_as_float(uz[e]) + sbv[128 + u] + sbh[128 + u];
                float ghn  = (hasH ? __uint_as_float(un[e]) : 0.0f) + sbh[256 + u];
                float gin  = __uint_as_float(ui[e]) + sbv[256 + u];
                if (useC2) {
                    rpre += C2T[(size_t)(nblk*384 + u)       * NB + rowg];
                    zpre += C2T[(size_t)(nblk*384 + 128 + u) * NB + rowg];
                    gin  += C2T[(size_t)(nblk*384 + 256 + u) * NB + rowg];
                }
                float r = 1.0f / (1.0f + expf(-rpre));
                float z = 1.0f / (1.0f + expf(-zpre));
                float n = tanhf(gin + r * ghn);
                hv[e] = (1.0f - z) * n + z * hv[e];
            }
            uint32_t wh[8], wl[8];
            #pragma unroll
            for (int q = 0; q < 8; q++) {
                __nv_bfloat16 h0 = __float2bfloat16(hv[2*q]);
                __nv_bfloat16 h1 = __float2bfloat16(hv[2*q+1]);
                wh[q] = pack2(h0, h1);
                wl[q] = pack2(__float2bfloat16(hv[2*q]   - __bfloat162float(h0)),
                              __float2bfloat16(hv[2*q+1] - __bfloat162float(h1)));
            }
            #pragma unroll
            for (int q = 0; q < 4; q++)
                *(float4*)(hrow + c0 + q*4) = *(float4*)(hv + q*4);
            *(uint4*)(ahr + c0)     = make_uint4(wh[0], wh[1], wh[2], wh[3]);
            *(uint4*)(ahr + c0 + 8) = make_uint4(wh[4], wh[5], wh[6], wh[7]);
            *(uint4*)(alr + c0)     = make_uint4(wl[0], wl[1], wl[2], wl[3]);
            *(uint4*)(alr + c0 + 8) = make_uint4(wl[4], wl[5], wl[6], wl[7]);
        }
    }
    TC_FENCE_BEFORE();
    __syncthreads();
    if (tid == 0) {
        mbar_inval(sb+16); mbar_inval(sb+24); mbar_inval(sb+32);
        mbar_inval(sb+40); mbar_inval(sb+48); mbar_inval(sb+56);
    }
    __syncthreads();
    if (wid == 0) { TC_RELINQUISH_CG2(); TC_DEALLOC_CG2(tmem, 512); }
    CLUSTER_SYNC();
#else
    // naive fallback (plain sm_103 pass; never selected at runtime on GB300)
    int rank = blockIdx.x & 1;
    for (int uu = tid; uu < 128 * 128; uu += 256) {
        int rowl = uu >> 7, jj = uu & 127;
        int rowg = rowblk * 256 + rank * 128 + rowl;
        float dots[3] = {0.f, 0.f, 0.f};
        if (nring > 0) {
            const __nv_bfloat16* arh = AhR + (size_t)rowg * HH;
            const __nv_bfloat16* arl = AlR + (size_t)rowg * HH;
            for (int g = 0; g < 3; g++) {
                size_t pr = (size_t)(nblk*384 + g*128 + jj) * HH;
                float s = 0.f;
                for (int k = 0; k < HH; k++) {
                    float a = __bfloat162float(arh[k]) + __bfloat162float(arl[k]);
                    float b = __bfloat162float(BhR[pr + k]) + __bfloat162float(BlR[pr + k]);
                    s += a * b;
                }
                dots[g] = s;
            }
        }
        if (mode == 1) {
            for (int g = 0; g < 3; g++)
                c2out[(size_t)(nblk*384 + g*128 + jj) * NB + rowg] = dots[g];
            continue;
        }
        float gi[3] = {0.f, 0.f, 0.f};
        for (int d = 0; d < DD; d++) {
            float x = pa[(size_t)rowg*DD + d] - pb[(size_t)rowg*DD + d];
            __nv_bfloat16 vh = __float2bfloat16(x);
            float vhf = __bfloat162float(vh);
            float vlf = __bfloat162float(__float2bfloat16(x - vhf));
            for (int g = 0; g < 3; g++) {
                size_t pr = (size_t)(nblk*384 + g*128 + jj) * 64;
                gi[g] += vhf * (__bfloat162float(MeAR[pr + d]) + __bfloat162float(MeAR[pr + 16 + d]))
                       + vlf * __bfloat162float(MeAR[pr + 32 + d]);
            }
        }
        int p0 = nblk*384 + jj;
        float rpre = gi[0] + dots[0] + bvp[p0]       + bhp[p0];
        float zpre = gi[1] + dots[1] + bvp[p0 + 128] + bhp[p0 + 128];
        float ghn  = dots[2] + bhp[p0 + 256];
        float gin  = gi[2]  + bvp[p0 + 256];
        if (useC2) {
            rpre += C2T[(size_t)p0 * NB + rowg];
            zpre += C2T[(size_t)(p0 + 128) * NB + rowg];
            gin  += C2T[(size_t)(p0 + 256) * NB + rowg];
        }
        float r = 1.0f / (1.0f + expf(-rpre));
        float z = 1.0f / (1.0f + expf(-zpre));
        float n = tanhf(gin + r * ghn);
        size_t hi = (size_t)rowg * HH + nblk*128 + jj;
        float hold = hasH ? hbuf[hi] : 0.0f;
        float hn = (1.0f - z) * n + z * hold;
        hbuf[hi] = hn;
        __nv_bfloat16 hb = __float2bfloat16(hn);
        oAh[hi] = hb;
        oAl[hi] = __float2bfloat16(hn - __bfloat162float(hb));
    }
#endif
}

// ---------------- prep kernels ----------------
__global__ void conv_all(const float* __restrict__ W1, const float* __restrict__ W2,
                         const float* __restrict__ Wd, const float* __restrict__ W2x,
                         __nv_bfloat16* __restrict__ h1, __nv_bfloat16* __restrict__ l1,
                         __nv_bfloat16* __restrict__ h2, __nv_bfloat16* __restrict__ l2,
                         __nv_bfloat16* __restrict__ hd, __nv_bfloat16* __restrict__ ld,
                         __nv_bfloat16* __restrict__ h2x, __nv_bfloat16* __restrict__ l2x) {
    int idx = blockIdx.x * blockDim.x + threadIdx.x;
    const int WN = G3 * HH;
    if (idx >= 4 * WN) return;
    int w = idx / WN, r = idx % WN;
    int p = r / HH, k = r % HH;
    int c = gatemap(p);
    float x;
    __nv_bfloat16 *hi, *lo;
    if (w == 0)      { x = W1[(size_t)c * HH + k];              hi = h1;  lo = l1; }
    else if (w == 1) { x = W2[(size_t)c * HH + k];              hi = h2;  lo = l2; }
    else if (w == 2) { x = Wd[(size_t)c * HH + k];              hi = hd;  lo = ld; }
    else             { x = W2x[(size_t)c * (EE + HH) + EE + k]; hi = h2x; lo = l2x; }
    __nv_bfloat16 h = __float2bfloat16(x);
    hi[r] = h;
    lo[r] = __float2bfloat16(x - __bfloat162float(h));
}

__global__ void prep_all(const float* __restrict__ W1, const float* __restrict__ W2,
                         const float* __restrict__ Wd,
                         const float* __restrict__ b1i, const float* __restrict__ b2i,
                         const float* __restrict__ bdi,
                         const float* __restrict__ bhh1, const float* __restrict__ bhh2,
                         const float* __restrict__ bhhd,
                         const float* __restrict__ embW, const float* __restrict__ embB,
                         __nv_bfloat16* __restrict__ MeA1, __nv_bfloat16* __restrict__ MeA2,
                         __nv_bfloat16* __restrict__ MeAd,
                         float* __restrict__ bv1, float* __restrict__ bh1,
                         float* __restrict__ bv2, float* __restrict__ bh2,
                         float* __restrict__ bvd, float* __restrict__ bhd) {
    int idx = blockIdx.x * blockDim.x + threadIdx.x;
    const int WN = G3 * 4;
    if (idx >= 3 * WN) return;
    int w = idx / WN, r = idx % WN;
    int p = r >> 2, q = r & 3;
    int c = gatemap(p);
    const float* wrow;
    const float *bin, *bhin;
    __nv_bfloat16 *MeA;
    float *bvo, *bho;
    if (w == 0)      { wrow = W1 + (size_t)c * EE;        bin = b1i; bhin = bhh1; MeA = MeA1; bvo = bv1; bho = bh1; }
    else if (w == 1) { wrow = W2 + (size_t)c * (EE + HH); bin = b2i; bhin = bhh2; MeA = MeA2; bvo = bv2; bho = bh2; }
    else             { wrow = Wd + (size_t)c * EE;        bin = bdi; bhin = bhhd; MeA = MeAd; bvo = bvd; bho = bhd; }
    float accM[4] = {0.f, 0.f, 0.f, 0.f};
    float accb = 0.0f;
    for (int e = 0; e < EE; e++) {
        float ww = wrow[e];
        const float* er = embW + e * DD + q * 4;
        accM[0] = fmaf(er[0], ww, accM[0]);
        accM[1] = fmaf(er[1], ww, accM[1]);
        accM[2] = fmaf(er[2], ww, accM[2]);
        accM[3] = fmaf(er[3], ww, accM[3]);
        if (q == 0) accb = fmaf(embB[e], ww, accb);
    }
    #pragma unroll
    for (int d2 = 0; d2 < 4; d2++) {
        int d = q * 4 + d2;
        float x = SCALEF * accM[d2];
        __nv_bfloat16 hi = __float2bfloat16(x);
        __nv_bfloat16 lo = __float2bfloat16(x - __bfloat162float(hi));
        MeA[(size_t)p*64 + d]      = hi;
        MeA[(size_t)p*64 + 16 + d] = lo;
        MeA[(size_t)p*64 + 32 + d] = hi;
        MeA[(size_t)p*64 + 48 + d] = __float2bfloat16(0.0f);
    }
    if (q == 0) { bvo[p] = accb + bin[c]; bho[p] = bhin[c]; }
}

// ---------------- decoder head ----------------
__global__ void h2n_pos(const float* __restrict__ h,
                        const float* __restrict__ h2nW, const float* __restrict__ h2nB,
                        const float* __restrict__ mixW, const float* __restrict__ mixB,
                        const float* __restrict__ base,
                        float* __restrict__ out_rel, float* __restrict__ out_pos) {
    int row = blockIdx.x;
    int tid = threadIdx.x;
    int warp = tid >> 5, lane = tid & 31;
    __shared__ float sn[5];
    if (warp < 5) {
        const float* hr = h + (size_t)row * HH;
        const float* wr = h2nW + warp * HH;
        float s = 0.0f;
        for (int i = lane; i < HH; i += 32) s = fmaf(hr[i], wr[i], s);
        #pragma unroll
        for (int o = 16; o > 0; o >>= 1) s += __shfl_down_sync(0xffffffffu, s, o);
        if (lane == 0) {
            float raw = s + h2nB[warp];
            float val;
            if (warp < 2) val = raw;
            else if (warp < 4) {
                float sp = raw > 0.0f ? raw + log1pf(expf(-raw)) : log1pf(expf(raw));
                val = 0.01f + 0.2f * sp;
            } else val = 0.7f * tanhf(raw);
            sn[warp] = val;
            out_rel[(size_t)row * 5 + warp] = val;
        }
    }
    __syncthreads();
    if (tid < DD) {
        float acc = mixB[tid];
        #pragma unroll
        for (int c = 0; c < 5; c++) acc = fmaf(sn[c], mixW[tid * 5 + c], acc);
        acc = acc > 0.0f ? acc : 0.0f;
        out_pos[(size_t)row * DD + tid] = base[(size_t)row * DD + tid] + acc;
    }
}

// ---------------- host: tensor maps ----------------
typedef CUresult (*PFN_tmEncode)(CUtensorMap*, CUtensorMapDataType, cuuint32_t, void*,
                                 const cuuint64_t*, const cuuint64_t*, const cuuint32_t*,
                                 const cuuint32_t*, CUtensorMapInterleave, CUtensorMapSwizzle,
                                 CUtensorMapL2promotion, CUtensorMapFloatOOBfill);
static PFN_tmEncode tm_encode_fn() {
    static PFN_tmEncode fn = nullptr;
    if (!fn) {
        void* p = nullptr;
        cudaDriverEntryPointQueryResult qr;
        cudaGetDriverEntryPoint("cuTensorMapEncodeTiled", &p, cudaEnableDefault, &qr);
        fn = (PFN_tmEncode)p;
    }
    return fn;
}
static void make_map(CUtensorMap* m, void* ptr, int rows, int cols, int boxw, int boxh) {
    cuuint64_t dims[2]    = {(cuuint64_t)cols, (cuuint64_t)rows};
    cuuint64_t strides[1] = {(cuuint64_t)cols * 2};
    cuuint32_t box[2]     = {(cuuint32_t)boxw, (cuuint32_t)boxh};
    cuuint32_t es[2]      = {1, 1};
    tm_encode_fn()(m, CU_TENSOR_MAP_DATA_TYPE_BFLOAT16, 2, ptr, dims, strides, box, es,
                   CU_TENSOR_MAP_INTERLEAVE_NONE, CU_TENSOR_MAP_SWIZZLE_128B,
                   CU_TENSOR_MAP_L2_PROMOTION_L2_128B, CU_TENSOR_MAP_FLOAT_OOB_FILL_NONE);
}

// ---------------- host orchestration ----------------
extern "C" void kernel_launch(void* const* d_in, const int* in_sizes, int n_in,
                              void* d_out, int out_size) {
    const float* observed = (const float*)d_in[0];
    const float* emb_W    = (const float*)d_in[1];
    const float* emb_b    = (const float*)d_in[2];
    const float* e1_Wih   = (const float*)d_in[3];
    const float* e1_Whh   = (const float*)d_in[4];
    const float* e1_bih   = (const float*)d_in[5];
    const float* e1_bhh   = (const float*)d_in[6];
    const float* e2_Wih   = (const float*)d_in[7];
    const float* e2_Whh   = (const float*)d_in[8];
    const float* e2_bih   = (const float*)d_in[9];
    const float* e2_bhh   = (const float*)d_in[10];
    const float* dec_Wih  = (const float*)d_in[11];
    const float* dec_Whh  = (const float*)d_in[12];
    const float* dec_bih  = (const float*)d_in[13];
    const float* dec_bhh  = (const float*)d_in[14];
    const float* h2n_W    = (const float*)d_in[15];
    const float* h2n_b    = (const float*)d_in[16];
    const float* mix_W    = (const float*)d_in[17];
    const float* mix_b    = (const float*)d_in[18];
    float* out = (float*)d_out;

    __nv_bfloat16 *Bh1,*Bl1,*Bh2,*Bl2,*Bhd,*Bld,*Bh2x,*Bl2x;
    __nv_bfloat16 *MeA1,*MeA2,*MeAd,*Ah,*Al;
    float *bv1,*bh1,*bv2,*bh2,*bvd,*bhd,*C2T,*h;
    cudaGetSymbolAddress((void**)&Bh1, g_Bh1);   cudaGetSymbolAddress((void**)&Bl1, g_Bl1);
    cudaGetSymbolAddress((void**)&Bh2, g_Bh2);   cudaGetSymbolAddress((void**)&Bl2, g_Bl2);
    cudaGetSymbolAddress((void**)&Bhd, g_Bhd);   cudaGetSymbolAddress((void**)&Bld, g_Bld);
    cudaGetSymbolAddress((void**)&Bh2x,g_Bh2x);  cudaGetSymbolAddress((void**)&Bl2x,g_Bl2x);
    cudaGetSymbolAddress((void**)&MeA1,g_MeA1);
    cudaGetSymbolAddress((void**)&MeA2,g_MeA2);
    cudaGetSymbolAddress((void**)&MeAd,g_MeAd);
    cudaGetSymbolAddress((void**)&Ah,  g_Ah);    cudaGetSymbolAddress((void**)&Al,  g_Al);
    cudaGetSymbolAddress((void**)&bv1, g_bv1);   cudaGetSymbolAddress((void**)&bh1, g_bh1);
    cudaGetSymbolAddress((void**)&bv2, g_bv2);   cudaGetSymbolAddress((void**)&bh2, g_bh2);
    cudaGetSymbolAddress((void**)&bvd, g_bvd);   cudaGetSymbolAddress((void**)&bhd, g_bhd);
    cudaGetSymbolAddress((void**)&C2T, g_C2T);
    cudaGetSymbolAddress((void**)&h,   g_h);

    CUtensorMap tAh, tAl;
    CUtensorMap tB1h, tB1l, tB2h, tB2l, tBdh, tBdl, tB2xh, tB2xl;
    CUtensorMap tMeA1, tMeA2, tMeAd;
    make_map(&tAh, Ah, NB, HH, 64, 128);
    make_map(&tAl, Al, NB, HH, 64, 128);
    make_map(&tB1h, Bh1, G3, HH, 64, 64);
    make_map(&tB1l, Bl1, G3, HH, 64, 64);
    make_map(&tB2h, Bh2, G3, HH, 64, 64);
    make_map(&tB2l, Bl2, G3, HH, 64, 64);
    make_map(&tBdh, Bhd, G3, HH, 64, 64);
    make_map(&tBdl, Bld, G3, HH, 64, 64);
    make_map(&tB2xh, Bh2x, G3, HH, 64, 64);
    make_map(&tB2xl, Bl2x, G3, HH, 64, 64);
    make_map(&tMeA1, MeA1, G3, 64, 64, 64);
    make_map(&tMeA2, MeA2, G3, 64, 64, 64);
    make_map(&tMeAd, MeAd, G3, 64, 64, 64);

    cudaFuncSetAttribute(gemm_gru, cudaFuncAttributeMaxDynamicSharedMemorySize, FUSED_SMEM);

    const int ND = NB * DD;
    float* rel_out  = out;
    float* pred_out = out + (size_t)NPRED * NB * 5;

    dim3 grid(2 * (G3 / 384), NB / 256);   // (12, 8)

    conv_all<<<(4 * G3 * HH + 255) / 256, 256>>>(
        e1_Whh, e2_Whh, dec_Whh, e2_Wih,
        Bh1, Bl1, Bh2, Bl2, Bhd, Bld, Bh2x, Bl2x);
    prep_all<<<(3 * G3 * 4 + 255) / 256, 256>>>(
        e1_Wih, e2_Wih, dec_Wih, e1_bih, e2_bih, dec_bih,
        e1_bhh, e2_bhh, dec_bhh, emb_W, emb_b,
        MeA1, MeA2, MeAd, bv1, bh1, bv2, bh2, bvd, bhd);

    // ---- encoder 1 (backward velocities) ----
    for (int t = 0; t < TT - 1; t++) {
        const float* pa = observed + (size_t)(7 - t) * ND;
        const float* pb = observed + (size_t)(6 - t) * ND;
        gemm_gru<<<grid, 256, FUSED_SMEM>>>(tAh, tAl, tB1h, tB1l, tMeA1,
            bv1, bh1, nullptr, pa, pb, h, Ah, Al, nullptr,
            Bh1, Bl1, MeA1, Ah, Al, (t > 0) ? 1 : 0, 0, 0);
    }
    // C2T = permuted(h_inv @ e2_Wih[:,256:]^T), transposed
    gemm_gru<<<grid, 256, FUSED_SMEM>>>(tAh, tAl, tB2xh, tB2xl, tMeA1,
        nullptr, nullptr, nullptr, nullptr, nullptr, h, Ah, Al, C2T,
        Bh2x, Bl2x, MeA1, Ah, Al, 1, 0, 1);

    // ---- encoder 2 (forward velocities) ----
    for (int t = 0; t < TT - 1; t++) {
        const float* pa = observed + (size_t)(t + 1) * ND;
        const float* pb = observed + (size_t)t * ND;
        gemm_gru<<<grid, 256, FUSED_SMEM>>>(tAh, tAl, tB2h, tB2l, tMeA2,
            bv2, bh2, C2T, pa, pb, h, Ah, Al, nullptr,
            Bh2, Bl2, MeA2, Ah, Al, (t > 0) ? 1 : 0, 1, 0);
    }

    // ---- decoder ----
    for (int k = 0; k < NPRED; k++) {
        const float *pa, *pb;
        if (k == 0)      { pa = observed + (size_t)7 * ND; pb = observed + (size_t)6 * ND; }
        else if (k == 1) { pa = pred_out;                  pb = observed + (size_t)7 * ND; }
        else             { pa = pred_out + (size_t)(k-1)*ND; pb = pred_out + (size_t)(k-2)*ND; }
        gemm_gru<<<grid, 256, FUSED_SMEM>>>(tAh, tAl, tBdh, tBdl, tMeAd,
            bvd, bhd, nullptr, pa, pb, h, Ah, Al, nullptr,
            Bhd, Bld, MeAd, Ah, Al, 1, 0, 0);
        h2n_pos<<<NB, 160>>>(h, h2n_W, h2n_b, mix_W, mix_b, pa,
                             rel_out + (size_t)k * NB * 5,
                             pred_out + (size_t)k * ND);
    }
}

// round 16
// speedup vs baseline: 1.1452x; 1.1452x over previous
#include <cuda_runtime.h>
#include <cuda.h>
#include <cuda_bf16.h>
#include <cstdint>
#include <math.h>

#define NB    2048
#define DD    16
#define EE    256
#define HH    768
#define G3    2304
#define TT    8
#define NPRED 12
#define SCALEF 4.0f

#if defined(__CUDA_ARCH_FEAT_SM103_ALL) || defined(__CUDA_ARCH_FEAT_SM100_ALL) || \
    (defined(__CUDA_ARCH_SPECIFIC__) && (__CUDA_ARCH_SPECIFIC__ >= 1000))
#define HAS_TCG 1
#else
#define HAS_TCG 0
#endif

// ---------------- device scratch ----------------
__device__ __align__(256) float g_M1[G3*DD];
__device__ __align__(256) float g_M2[G3*DD];
__device__ __align__(256) float g_Md[G3*DD];
__device__ __align__(256) float g_b1[G3];
__device__ __align__(256) float g_b2[G3];
__device__ __align__(256) float g_bd[G3];
__device__ __align__(256) __nv_bfloat16 g_Bh1[G3*HH];
__device__ __align__(256) __nv_bfloat16 g_Bl1[G3*HH];
__device__ __align__(256) __nv_bfloat16 g_Bh2[G3*HH];
__device__ __align__(256) __nv_bfloat16 g_Bl2[G3*HH];
__device__ __align__(256) __nv_bfloat16 g_Bhd[G3*HH];
__device__ __align__(256) __nv_bfloat16 g_Bld[G3*HH];
__device__ __align__(256) __nv_bfloat16 g_Bh2x[G3*HH];
__device__ __align__(256) __nv_bfloat16 g_Bl2x[G3*HH];
__device__ __align__(256) __nv_bfloat16 g_Ah[NB*HH];
__device__ __align__(256) __nv_bfloat16 g_Al[NB*HH];
__device__ __align__(256) float g_C2[NB*G3];
__device__ __align__(256) float g_G[NB*G3];
__device__ __align__(256) float g_h[NB*HH];

// ---------------- helpers ----------------
__device__ __forceinline__ uint32_t smem_u32(const void* p) {
    uint32_t a;
    asm("{ .reg .u64 t; cvta.to.shared.u64 t, %1; cvt.u32.u64 %0, t; }" : "=r"(a) : "l"(p));
    return a;
}
__device__ __forceinline__ uint32_t elect_one() {
    uint32_t pred;
    asm volatile("{\n\t.reg .pred p;\n\telect.sync _|p, 0xFFFFFFFF;\n\t"
                 "selp.b32 %0, 1, 0, p;\n\t}" : "=r"(pred));
    return pred;
}
__device__ __forceinline__ void mbar_init(uint32_t m, uint32_t c) {
    asm volatile("mbarrier.init.shared.b64 [%0], %1;" :: "r"(m), "r"(c) : "memory");
}
__device__ __forceinline__ void mbar_inval(uint32_t m) {
    asm volatile("mbarrier.inval.shared.b64 [%0];" :: "r"(m) : "memory");
}
__device__ __forceinline__ void mbar_wait(uint32_t m, uint32_t par) {
    uint32_t done;
    asm volatile("{\n\t.reg .pred p;\n\t"
        "mbarrier.try_wait.parity.acquire.cta.shared::cta.b64 p, [%1], %2;\n\t"
        "selp.b32 %0, 1, 0, p;\n\t}" : "=r"(done) : "r"(m), "r"(par) : "memory");
    while (!done) {
        asm volatile("{\n\t.reg .pred p;\n\t"
            "mbarrier.try_wait.parity.acquire.cta.shared::cta.b64 p, [%1], %2, 0x989680;\n\t"
            "selp.b32 %0, 1, 0, p;\n\t}" : "=r"(done) : "r"(m), "r"(par) : "memory");
    }
}

#if HAS_TCG
#define TC_ALLOC(s, n)   asm volatile("tcgen05.alloc.cta_group::1.sync.aligned.shared::cta.b32 [%0], %1;" :: "r"(s), "r"((uint32_t)(n)) : "memory")
#define TC_DEALLOC(t, n) asm volatile("tcgen05.dealloc.cta_group::1.sync.aligned.b32 %0, %1;" :: "r"(t), "r"((uint32_t)(n)))
#define TC_RELINQUISH()  asm volatile("tcgen05.relinquish_alloc_permit.cta_group::1.sync.aligned;")
#define TC_COMMIT(m)     asm volatile("tcgen05.commit.cta_group::1.mbarrier::arrive::one.shared::cluster.b64 [%0];" :: "r"(m) : "memory")
#define TC_FENCE_AFTER()  asm volatile("tcgen05.fence::after_thread_sync;" ::: "memory")
#define TC_FENCE_BEFORE() asm volatile("tcgen05.fence::before_thread_sync;" ::: "memory")
#define TC_WAIT_LD()      asm volatile("tcgen05.wait::ld.sync.aligned;" ::: "memory")

#define TC_LD_X32(r, addr) \
    asm volatile("tcgen05.ld.sync.aligned.32x32b.x32.b32 " \
        "{%0, %1, %2, %3, %4, %5, %6, %7, " \
        " %8, %9, %10, %11, %12, %13, %14, %15, " \
        " %16, %17, %18, %19, %20, %21, %22, %23, " \
        " %24, %25, %26, %27, %28, %29, %30, %31}, [%32];" \
        : "=r"((r)[0]),  "=r"((r)[1]),  "=r"((r)[2]),  "=r"((r)[3]), \
          "=r"((r)[4]),  "=r"((r)[5]),  "=r"((r)[6]),  "=r"((r)[7]), \
          "=r"((r)[8]),  "=r"((r)[9]),  "=r"((r)[10]), "=r"((r)[11]), \
          "=r"((r)[12]), "=r"((r)[13]), "=r"((r)[14]), "=r"((r)[15]), \
          "=r"((r)[16]), "=r"((r)[17]), "=r"((r)[18]), "=r"((r)[19]), \
          "=r"((r)[20]), "=r"((r)[21]), "=r"((r)[22]), "=r"((r)[23]), \
          "=r"((r)[24]), "=r"((r)[25]), "=r"((r)[26]), "=r"((r)[27]), \
          "=r"((r)[28]), "=r"((r)[29]), "=r"((r)[30]), "=r"((r)[31]) \
        : "r"(addr))

__device__ __forceinline__ void mma_bf16_ss(uint32_t d, uint64_t ad, uint64_t bd,
                                            uint32_t idesc, uint32_t en) {
    asm volatile("{\n\t.reg .pred p;\n\tsetp.ne.u32 p, %5, 0;\n\t"
        "tcgen05.mma.cta_group::1.kind::f16 [%0], %1, %2, %3, {%4, %4, %4, %4}, p;\n\t}"
        :: "r"(d), "l"(ad), "l"(bd), "r"(idesc), "r"(0u), "r"(en) : "memory");
}
#define MMA_IDESC ((1u<<4) | (1u<<7) | (1u<<10) | ((128u/8u)<<17) | ((128u/16u)<<24))

__device__ __forceinline__ uint64_t make_desc_sw128(uint32_t addr) {
    const uint64_t base =
        (uint64_t(2) << 61) | (uint64_t(1) << 46) | (uint64_t(64) << 32) | (uint64_t(1) << 16);
    return base | ((uint64_t)(addr >> 4) & 0x3FFF);
}

#define MBAR_EXPECT_TX(m, bytes) \
    asm volatile("mbarrier.arrive.expect_tx.shared.b64 _, [%0], %1;" \
                 :: "r"(m), "r"((uint32_t)(bytes)) : "memory")
#define TMA_LD_2D(dst, map, x, y, mbar) \
    asm volatile("cp.async.bulk.tensor.2d.shared::cta.global.tile.mbarrier::complete_tx::bytes " \
                 "[%0], [%1, {%2, %3}], [%4];" \
                 :: "r"(dst), "l"(map), "r"(x), "r"(y), "r"(mbar) : "memory")
#endif

// ---------------- GEMM: C(2048x2304) = A(2048x768) @ B(2304x768)^T -----------
// KC=64, SW128, 2 stages, warp-specialized producer(warp1)/consumer(warp0).
#define KC      64
#define NCHUNK  (HH / KC)             // 12
#define TILEB   16384                 // 128 rows x 128B
#define STAGEB  (6 * TILEB)
#define GEMM_SMEM (1024 + 2 * STAGEB) // 197632

__global__ void __launch_bounds__(256, 1)
gemm_tc(const __grid_constant__ CUtensorMap mAh, const __grid_constant__ CUtensorMap mAl,
        const __grid_constant__ CUtensorMap mBh, const __grid_constant__ CUtensorMap mBl,
        const __nv_bfloat16* __restrict__ Ahg, const __nv_bfloat16* __restrict__ Alg,
        const __nv_bfloat16* __restrict__ Bhg, const __nv_bfloat16* __restrict__ Blg,
        float* __restrict__ C) {
    extern __shared__ char smem[];
    int tid = threadIdx.x, wid = tid >> 5, lane = tid & 31;
#if HAS_TCG
    uint32_t sb = smem_u32(smem);
    if (wid == 0) TC_ALLOC(sb, 512);
    if (tid == 0) {
        mbar_init(sb+16,1); mbar_init(sb+24,1);
        mbar_init(sb+32,1); mbar_init(sb+40,1);
    }
    __syncthreads();
    uint32_t tmem;
    asm volatile("ld.shared.b32 %0, [%1];" : "=r"(tmem) : "r"(sb));

    int arow = blockIdx.y * 128;
    int brow = blockIdx.x * 256;

    if (wid == 1 && elect_one()) {
        // -------- producer: TMA only --------
        for (int i = 0; i < NCHUNK; i++) {
            int slot = i & 1;
            uint32_t stgu = sb + 1024 + slot * STAGEB;
            uint32_t fb = sb + 16 + 8 * slot;
            if (i >= 2) mbar_wait(sb + 32 + 8 * slot, ((i - 2) >> 1) & 1);
            MBAR_EXPECT_TX(fb, 6 * TILEB);
            int kc0 = i * KC;
            TMA_LD_2D(stgu,           &mAh, kc0, arow,       fb);
            TMA_LD_2D(stgu + TILEB,   &mAl, kc0, arow,       fb);
            TMA_LD_2D(stgu + 2*TILEB, &mBh, kc0, brow,       fb);
            TMA_LD_2D(stgu + 3*TILEB, &mBl, kc0, brow,       fb);
            TMA_LD_2D(stgu + 4*TILEB, &mBh, kc0, brow + 128, fb);
            TMA_LD_2D(stgu + 5*TILEB, &mBl, kc0, brow + 128, fb);
        }
    } else if (wid == 0 && elect_one()) {
        // -------- consumer: MMA only --------
        for (int i = 0; i < NCHUNK; i++) {
            int slot = i & 1;
            uint32_t stgu = sb + 1024 + slot * STAGEB;
            mbar_wait(sb + 16 + 8 * slot, (i >> 1) & 1);

            uint64_t dAh  = make_desc_sw128(stgu);
            uint64_t dAl  = make_desc_sw128(stgu + TILEB);
            uint64_t dBh0 = make_desc_sw128(stgu + 2*TILEB);
            uint64_t dBl0 = make_desc_sw128(stgu + 3*TILEB);
            uint64_t dBh1 = make_desc_sw128(stgu + 4*TILEB);
            uint64_t dBl1 = make_desc_sw128(stgu + 5*TILEB);
            uint32_t first = (i == 0) ? 0u : 1u;
            #pragma unroll
            for (int s = 0; s < 4; s++) {
                uint64_t o = (uint64_t)(s * 2);
                uint32_t en0 = (s == 0) ? first : 1u;
                mma_bf16_ss(tmem,       dAh + o, dBh0 + o, MMA_IDESC, en0);
                mma_bf16_ss(tmem,       dAh + o, dBl0 + o, MMA_IDESC, 1u);
                mma_bf16_ss(tmem,       dAl + o, dBh0 + o, MMA_IDESC, 1u);
                mma_bf16_ss(tmem + 128, dAh + o, dBh1 + o, MMA_IDESC, en0);
                mma_bf16_ss(tmem + 128, dAh + o, dBl1 + o, MMA_IDESC, 1u);
                mma_bf16_ss(tmem + 128, dAl + o, dBh1 + o, MMA_IDESC, 1u);
            }
            TC_COMMIT(sb + 32 + 8 * slot);
        }
        mbar_wait(sb + 32, 1);
        mbar_wait(sb + 40, 1);
    }
    __syncthreads();
    TC_FENCE_AFTER();

    int sub = wid & 3, half = wid >> 2;
    int rowg = blockIdx.y * 128 + sub * 32 + lane;
    float* crow = C + (size_t)rowg * G3 + blockIdx.x * 256 + half * 128;
    #pragma unroll
    for (int part = 0; part < 2; part++) {
        uint32_t r0[32], r1[32];
        TC_LD_X32(r0, tmem + half * 128 + part * 64);
        TC_LD_X32(r1, tmem + half * 128 + part * 64 + 32);
        TC_WAIT_LD();
        #pragma unroll
        for (int c = 0; c < 32; c += 4) {
            *(float4*)(crow + part*64 + c) = make_float4(
                __uint_as_float(r0[c]),   __uint_as_float(r0[c+1]),
                __uint_as_float(r0[c+2]), __uint_as_float(r0[c+3]));
            *(float4*)(crow + part*64 + 32 + c) = make_float4(
                __uint_as_float(r1[c]),   __uint_as_float(r1[c+1]),
                __uint_as_float(r1[c+2]), __uint_as_float(r1[c+3]));
        }
    }
    TC_FENCE_BEFORE();
    __syncthreads();
    if (tid == 0) {
        mbar_inval(sb+16); mbar_inval(sb+24);
        mbar_inval(sb+32); mbar_inval(sb+40);
    }
    __syncthreads();
    if (wid == 0) { TC_RELINQUISH(); TC_DEALLOC(tmem, 512); }
#else
    // FFMA fallback (plain sm_103 pass only; never selected at runtime on GB300)
    float* As = (float*)smem;
    float* Bs = As + 16 * 128;
    int ty = tid >> 4, tx = tid & 15;
    const __nv_bfloat16* Ahb = Ahg + (size_t)blockIdx.y * 128 * HH;
    const __nv_bfloat16* Alb = Alg + (size_t)blockIdx.y * 128 * HH;
    for (int nb = 0; nb < 2; nb++) {
        const __nv_bfloat16* Bhb = Bhg + (size_t)(blockIdx.x * 256 + nb * 128) * HH;
        const __nv_bfloat16* Blb = Blg + (size_t)(blockIdx.x * 256 + nb * 128) * HH;
        float acc[8][8];
        #pragma unroll
        for (int i = 0; i < 8; i++)
            #pragma unroll
            for (int j = 0; j < 8; j++) acc[i][j] = 0.0f;
        for (int kt = 0; kt < HH; kt += 16) {
            {
                int r = tid >> 1, kq = (tid & 1) * 8;
                size_t go = (size_t)r * HH + kt + kq;
                uint4 vh = *(const uint4*)(Ahb + go);
                uint4 vl = *(const uint4*)(Alb + go);
                const __nv_bfloat16* ph = (const __nv_bfloat16*)&vh;
                const __nv_bfloat16* pl = (const __nv_bfloat16*)&vl;
                #pragma unroll
                for (int e = 0; e < 8; e++)
                    As[(kq + e) * 128 + r] = __bfloat162float(ph[e]) + __bfloat162float(pl[e]);
            }
            {
                int n = tid >> 1, kq = (tid & 1) * 8;
                size_t go = (size_t)n * HH + kt + kq;
                uint4 vh = *(const uint4*)(Bhb + go);
                uint4 vl = *(const uint4*)(Blb + go);
                const __nv_bfloat16* ph = (const __nv_bfloat16*)&vh;
                const __nv_bfloat16* pl = (const __nv_bfloat16*)&vl;
                #pragma unroll
                for (int e = 0; e < 8; e++)
                    Bs[(kq + e) * 128 + n] = __bfloat162float(ph[e]) + __bfloat162float(pl[e]);
            }
            __syncthreads();
            #pragma unroll
            for (int k = 0; k < 16; k++) {
                float ar[8], br[8];
                #pragma unroll
                for (int e = 0; e < 8; e++) ar[e] = As[k * 128 + ty * 8 + e];
                #pragma unroll
                for (int e = 0; e < 8; e++) br[e] = Bs[k * 128 + tx * 8 + e];
                #pragma unroll
                for (int i = 0; i < 8; i++)
                    #pragma unroll
                    for (int j = 0; j < 8; j++)
                        acc[i][j] = fmaf(ar[i], br[j], acc[i][j]);
            }
            __syncthreads();
        }
        int rowBase = blockIdx.y * 128 + ty * 8;
        int colBase = blockIdx.x * 256 + nb * 128 + tx * 8;
        #pragma unroll
        for (int i = 0; i < 8; i++) {
            *(float4*)(C + (size_t)(rowBase + i) * G3 + colBase) =
                make_float4(acc[i][0], acc[i][1], acc[i][2], acc[i][3]);
            *(float4*)(C + (size_t)(rowBase + i) * G3 + colBase + 4) =
                make_float4(acc[i][4], acc[i][5], acc[i][6], acc[i][7]);
        }
        __syncthreads();
    }
#endif
}

// ---------------- batched prep kernels ----------------
__global__ void conv_all(const float* __restrict__ W1, const float* __restrict__ W2,
                         const float* __restrict__ Wd, const float* __restrict__ W2x,
                         __nv_bfloat16* __restrict__ h1, __nv_bfloat16* __restrict__ l1,
                         __nv_bfloat16* __restrict__ h2, __nv_bfloat16* __restrict__ l2,
                         __nv_bfloat16* __restrict__ hd, __nv_bfloat16* __restrict__ ld,
                         __nv_bfloat16* __restrict__ h2x, __nv_bfloat16* __restrict__ l2x) {
    int idx = blockIdx.x * blockDim.x + threadIdx.x;
    const int WN = G3 * HH;
    if (idx >= 4 * WN) return;
    int w = idx / WN, r = idx % WN;
    int j = r / HH, k = r % HH;
    float x;
    __nv_bfloat16 *hi, *lo;
    if (w == 0)      { x = W1[(size_t)j * HH + k];              hi = h1;  lo = l1; }
    else if (w == 1) { x = W2[(size_t)j * HH + k];              hi = h2;  lo = l2; }
    else if (w == 2) { x = Wd[(size_t)j * HH + k];              hi = hd;  lo = ld; }
    else             { x = W2x[(size_t)j * (EE + HH) + EE + k]; hi = h2x; lo = l2x; }
    __nv_bfloat16 h = __float2bfloat16(x);
    hi[r] = h;
    lo[r] = __float2bfloat16(x - __bfloat162float(h));
}

__global__ void prep_all(const float* __restrict__ W1, const float* __restrict__ W2,
                         const float* __restrict__ Wd,
                         const float* __restrict__ b1i, const float* __restrict__ b2i,
                         const float* __restrict__ bdi,
                         const float* __restrict__ embW, const float* __restrict__ embB,
                         float* __restrict__ M1, float* __restrict__ M2, float* __restrict__ Md,
                         float* __restrict__ b1o, float* __restrict__ b2o, float* __restrict__ bdo) {
    int idx = blockIdx.x * blockDim.x + threadIdx.x;
    const int WN = G3 * 4;
    if (idx >= 3 * WN) return;
    int w = idx / WN, r = idx % WN;
    int p = r >> 2, q = r & 3;
    const float* wrow;
    const float* bin;
    float *MT, *bout;
    if (w == 0)      { wrow = W1 + (size_t)p * EE;        bin = b1i; MT = M1; bout = b1o; }
    else if (w == 1) { wrow = W2 + (size_t)p * (EE + HH); bin = b2i; MT = M2; bout = b2o; }
    else             { wrow = Wd + (size_t)p * EE;        bin = bdi; MT = Md; bout = bdo; }
    float accM[4] = {0.f, 0.f, 0.f, 0.f};
    float accb = 0.0f;
    for (int e = 0; e < EE; e++) {
        float ww = wrow[e];
        const float* er = embW + e * DD + q * 4;
        accM[0] = fmaf(er[0], ww, accM[0]);
        accM[1] = fmaf(er[1], ww, accM[1]);
        accM[2] = fmaf(er[2], ww, accM[2]);
        accM[3] = fmaf(er[3], ww, accM[3]);
        if (q == 0) accb = fmaf(embB[e], ww, accb);
    }
    *(float4*)(MT + (size_t)p * DD + q * 4) =
        make_float4(SCALEF*accM[0], SCALEF*accM[1], SCALEF*accM[2], SCALEF*accM[3]);
    if (q == 0) bout[p] = accb + bin[p];
}

// ---------------- GRU update: 8-row batch, MT coalesced, grid (3,256) -------
#define GRU_ROWS 8
__global__ void __launch_bounds__(256)
gru_update(const float* __restrict__ MT, const float* __restrict__ bvec,
           const float* __restrict__ bhh, const float* __restrict__ C2,
           const float* __restrict__ G,
           const float* __restrict__ pa, const float* __restrict__ pb,
           float* __restrict__ h,
           __nv_bfloat16* __restrict__ ah, __nv_bfloat16* __restrict__ al) {
    int tid = threadIdx.x;
    int j = blockIdx.x * 256 + tid;
    int row0 = blockIdx.y * GRU_ROWS;

    __shared__ float sv[GRU_ROWS][DD];
    if (tid < GRU_ROWS * DD) {
        int r = tid >> 4, d = tid & 15;
        sv[r][d] = pa[(size_t)(row0 + r) * DD + d] - pb[(size_t)(row0 + r) * DD + d];
    }
    __syncthreads();

    float4 m[3][4];
    #pragma unroll
    for (int g = 0; g < 3; g++)
        #pragma unroll
        for (int q = 0; q < 4; q++)
            m[g][q] = *(const float4*)(MT + (size_t)(g * HH + j) * DD + q * 4);

    float bvr = bvec[j], bvz = bvec[j + HH], bvn = bvec[j + 2 * HH];
    float bhr = bhh[j],  bhz = bhh[j + HH],  bhn = bhh[j + 2 * HH];

    #pragma unroll
    for (int r = 0; r < GRU_ROWS; r++) {
        int row = row0 + r;
        size_t idx = (size_t)row * HH + j;
        float gi_r = bvr, gi_z = bvz, gi_n = bvn;
        #pragma unroll
        for (int q = 0; q < 4; q++) {
            float v0 = sv[r][q*4], v1 = sv[r][q*4+1], v2 = sv[r][q*4+2], v3 = sv[r][q*4+3];
            gi_r = fmaf(v0, m[0][q].x, fmaf(v1, m[0][q].y, fmaf(v2, m[0][q].z, fmaf(v3, m[0][q].w, gi_r))));
            gi_z = fmaf(v0, m[1][q].x, fmaf(v1, m[1][q].y, fmaf(v2, m[1][q].z, fmaf(v3, m[1][q].w, gi_z))));
            gi_n = fmaf(v0, m[2][q].x, fmaf(v1, m[2][q].y, fmaf(v2, m[2][q].z, fmaf(v3, m[2][q].w, gi_n))));
        }
        if (C2 != nullptr) {
            const float* c = C2 + (size_t)row * G3;
            gi_r += c[j];
            gi_z += c[j + HH];
            gi_n += c[j + 2 * HH];
        }
        float gh_r = bhr, gh_z = bhz, gh_n = bhn;
        float ho = 0.0f;
        if (G != nullptr) {
            const float* grow = G + (size_t)row * G3;
            gh_r += grow[j];
            gh_z += grow[j + HH];
            gh_n += grow[j + 2 * HH];
            ho = h[idx];
        }
        float rr = 1.0f / (1.0f + expf(-(gi_r + gh_r)));
        float zz = 1.0f / (1.0f + expf(-(gi_z + gh_z)));
        float nn = tanhf(gi_n + rr * gh_n);
        float hn = (1.0f - zz) * nn + zz * ho;
        h[idx] = hn;
        __nv_bfloat16 hb = __float2bfloat16(hn);
        ah[idx] = hb;
        al[idx] = __float2bfloat16(hn - __bfloat162float(hb));
    }
}

// ---------------- decoder head: one warp per row, h read once ---------------
__global__ void __launch_bounds__(256)
h2n_pos(const float* __restrict__ h,
        const float* __restrict__ h2nW, const float* __restrict__ h2nB,
        const float* __restrict__ mixW, const float* __restrict__ mixB,
        const float* __restrict__ base,
        float* __restrict__ out_rel, float* __restrict__ out_pos) {
    int w = threadIdx.x >> 5, lane = threadIdx.x & 31;
    int row = blockIdx.x * 8 + w;

    const float* hr = h + (size_t)row * HH;
    float s0 = 0.f, s1 = 0.f, s2 = 0.f, s3 = 0.f, s4 = 0.f;
    for (int i = lane; i < HH; i += 32) {
        float hv = hr[i];
        s0 = fmaf(hv, h2nW[i],          s0);
        s1 = fmaf(hv, h2nW[HH + i],     s1);
        s2 = fmaf(hv, h2nW[2*HH + i],   s2);
        s3 = fmaf(hv, h2nW[3*HH + i],   s3);
        s4 = fmaf(hv, h2nW[4*HH + i],   s4);
    }
    #pragma unroll
    for (int o = 16; o > 0; o >>= 1) {
        s0 += __shfl_down_sync(0xffffffffu, s0, o);
        s1 += __shfl_down_sync(0xffffffffu, s1, o);
        s2 += __shfl_down_sync(0xffffffffu, s2, o);
        s3 += __shfl_down_sync(0xffffffffu, s3, o);
        s4 += __shfl_down_sync(0xffffffffu, s4, o);
    }
    float v0, v1, v2, v3, v4;
    if (lane == 0) {
        v0 = s0 + h2nB[0];
        v1 = s1 + h2nB[1];
        float r2 = s2 + h2nB[2];
        float r3 = s3 + h2nB[3];
        float r4 = s4 + h2nB[4];
        float sp2 = r2 > 0.0f ? r2 + log1pf(expf(-r2)) : log1pf(expf(r2));
        float sp3 = r3 > 0.0f ? r3 + log1pf(expf(-r3)) : log1pf(expf(r3));
        v2 = 0.01f + 0.2f * sp2;
        v3 = 0.01f + 0.2f * sp3;
        v4 = 0.7f * tanhf(r4);
        float* ro = out_rel + (size_t)row * 5;
        ro[0] = v0; ro[1] = v1; ro[2] = v2; ro[3] = v3; ro[4] = v4;
    }
    v0 = __shfl_sync(0xffffffffu, v0, 0);
    v1 = __shfl_sync(0xffffffffu, v1, 0);
    v2 = __shfl_sync(0xffffffffu, v2, 0);
    v3 = __shfl_sync(0xffffffffu, v3, 0);
    v4 = __shfl_sync(0xffffffffu, v4, 0);
    if (lane < DD) {
        float acc = mixB[lane];
        const float* mw = mixW + lane * 5;
        acc = fmaf(v0, mw[0], acc);
        acc = fmaf(v1, mw[1], acc);
        acc = fmaf(v2, mw[2], acc);
        acc = fmaf(v3, mw[3], acc);
        acc = fmaf(v4, mw[4], acc);
        acc = acc > 0.0f ? acc : 0.0f;
        out_pos[(size_t)row * DD + lane] = base[(size_t)row * DD + lane] + acc;
    }
}

// ---------------- host: tensor-map creation ----------------
typedef CUresult (*PFN_tmEncode)(CUtensorMap*, CUtensorMapDataType, cuuint32_t, void*,
                                 const cuuint64_t*, const cuuint64_t*, const cuuint32_t*,
                                 const cuuint32_t*, CUtensorMapInterleave, CUtensorMapSwizzle,
                                 CUtensorMapL2promotion, CUtensorMapFloatOOBfill);

static PFN_tmEncode tm_encode_fn() {
    static PFN_tmEncode fn = nullptr;
    if (!fn) {
        void* p = nullptr;
        cudaDriverEntryPointQueryResult qr;
        cudaGetDriverEntryPoint("cuTensorMapEncodeTiled", &p, cudaEnableDefault, &qr);
        fn = (PFN_tmEncode)p;
    }
    return fn;
}

static void make_map_bf16(CUtensorMap* m, void* ptr, int rows) {
    cuuint64_t dims[2]    = {(cuuint64_t)HH, (cuuint64_t)rows};
    cuuint64_t strides[1] = {(cuuint64_t)HH * 2};
    cuuint32_t box[2]     = {64, 128};
    cuuint32_t es[2]      = {1, 1};
    tm_encode_fn()(m, CU_TENSOR_MAP_DATA_TYPE_BFLOAT16, 2, ptr, dims, strides, box, es,
                   CU_TENSOR_MAP_INTERLEAVE_NONE, CU_TENSOR_MAP_SWIZZLE_128B,
                   CU_TENSOR_MAP_L2_PROMOTION_L2_128B, CU_TENSOR_MAP_FLOAT_OOB_FILL_NONE);
}

// ---------------- host orchestration ----------------
extern "C" void kernel_launch(void* const* d_in, const int* in_sizes, int n_in,
                              void* d_out, int out_size) {
    const float* observed = (const float*)d_in[0];
    const float* emb_W    = (const float*)d_in[1];
    const float* emb_b    = (const float*)d_in[2];
    const float* e1_Wih   = (const float*)d_in[3];
    const float* e1_Whh   = (const float*)d_in[4];
    const float* e1_bih   = (const float*)d_in[5];
    const float* e1_bhh   = (const float*)d_in[6];
    const float* e2_Wih   = (const float*)d_in[7];
    const float* e2_Whh   = (const float*)d_in[8];
    const float* e2_bih   = (const float*)d_in[9];
    const float* e2_bhh   = (const float*)d_in[10];
    const float* dec_Wih  = (const float*)d_in[11];
    const float* dec_Whh  = (const float*)d_in[12];
    const float* dec_bih  = (const float*)d_in[13];
    const float* dec_bhh  = (const float*)d_in[14];
    const float* h2n_W    = (const float*)d_in[15];
    const float* h2n_b    = (const float*)d_in[16];
    const float* mix_W    = (const float*)d_in[17];
    const float* mix_b    = (const float*)d_in[18];
    float* out = (float*)d_out;

    float *M1, *M2, *Md, *b1, *b2, *bd, *C2, *G, *h;
    __nv_bfloat16 *Bh1, *Bl1, *Bh2, *Bl2, *Bhd, *Bld, *Bh2x, *Bl2x, *Ah, *Al;
    cudaGetSymbolAddress((void**)&M1,  g_M1);
    cudaGetSymbolAddress((void**)&M2,  g_M2);
    cudaGetSymbolAddress((void**)&Md,  g_Md);
    cudaGetSymbolAddress((void**)&b1,  g_b1);
    cudaGetSymbolAddress((void**)&b2,  g_b2);
    cudaGetSymbolAddress((void**)&bd,  g_bd);
    cudaGetSymbolAddress((void**)&Bh1, g_Bh1);
    cudaGetSymbolAddress((void**)&Bl1, g_Bl1);
    cudaGetSymbolAddress((void**)&Bh2, g_Bh2);
    cudaGetSymbolAddress((void**)&Bl2, g_Bl2);
    cudaGetSymbolAddress((void**)&Bhd, g_Bhd);
    cudaGetSymbolAddress((void**)&Bld, g_Bld);
    cudaGetSymbolAddress((void**)&Bh2x,g_Bh2x);
    cudaGetSymbolAddress((void**)&Bl2x,g_Bl2x);
    cudaGetSymbolAddress((void**)&Ah,  g_Ah);
    cudaGetSymbolAddress((void**)&Al,  g_Al);
    cudaGetSymbolAddress((void**)&C2,  g_C2);
    cudaGetSymbolAddress((void**)&G,   g_G);
    cudaGetSymbolAddress((void**)&h,   g_h);

    CUtensorMap tAh, tAl, tB1h, tB1l, tB2h, tB2l, tBdh, tBdl, tB2xh, tB2xl;
    make_map_bf16(&tAh,  Ah,  NB);
    make_map_bf16(&tAl,  Al,  NB);
    make_map_bf16(&tB1h, Bh1, G3);
    make_map_bf16(&tB1l, Bl1, G3);
    make_map_bf16(&tB2h, Bh2, G3);
    make_map_bf16(&tB2l, Bl2, G3);
    make_map_bf16(&tBdh, Bhd, G3);
    make_map_bf16(&tBdl, Bld, G3);
    make_map_bf16(&tB2xh, Bh2x, G3);
    make_map_bf16(&tB2xl, Bl2x, G3);

    cudaFuncSetAttribute(gemm_tc, cudaFuncAttributeMaxDynamicSharedMemorySize, GEMM_SMEM);

    const int ND = NB * DD;
    float* rel_out  = out;
    float* pred_out = out + (size_t)NPRED * NB * 5;

    dim3 gemmGrid(G3 / 256, NB / 128);        // (9,16)
    dim3 gruGrid(HH / 256, NB / GRU_ROWS);    // (3,256)

    conv_all<<<(4 * G3 * HH + 255) / 256, 256>>>(
        e1_Whh, e2_Whh, dec_Whh, e2_Wih,
        Bh1, Bl1, Bh2, Bl2, Bhd, Bld, Bh2x, Bl2x);
    prep_all<<<(3 * G3 * 4 + 255) / 256, 256>>>(
        e1_Wih, e2_Wih, dec_Wih, e1_bih, e2_bih, dec_bih,
        emb_W, emb_b, M1, M2, Md, b1, b2, bd);

    // ---- encoder 1 (backward velocities) ----
    for (int t = 0; t < TT - 1; t++) {
        const float* pa = observed + (size_t)(7 - t) * ND;
        const float* pb = observed + (size_t)(6 - t) * ND;
        const float* Gp = nullptr;
        if (t > 0) {
            gemm_tc<<<gemmGrid, 256, GEMM_SMEM>>>(tAh, tAl, tB1h, tB1l, Ah, Al, Bh1, Bl1, G);
            Gp = G;
        }
        gru_update<<<gruGrid, 256>>>(M1, b1, e1_bhh, nullptr, Gp, pa, pb, h, Ah, Al);
    }

    // C2 = h_inv @ e2_Wih[:,256:]^T
    gemm_tc<<<gemmGrid, 256, GEMM_SMEM>>>(tAh, tAl, tB2xh, tB2xl, Ah, Al, Bh2x, Bl2x, C2);

    // ---- encoder 2 (forward velocities) ----
    for (int t = 0; t < TT - 1; t++) {
        const float* pa = observed + (size_t)(t + 1) * ND;
        const float* pb = observed + (size_t)t * ND;
        const float* Gp = nullptr;
        if (t > 0) {
            gemm_tc<<<gemmGrid, 256, GEMM_SMEM>>>(tAh, tAl, tB2h, tB2l, Ah, Al, Bh2, Bl2, G);
            Gp = G;
        }
        gru_update<<<gruGrid, 256>>>(M2, b2, e2_bhh, C2, Gp, pa, pb, h, Ah, Al);
    }

    // ---- decoder ----
    for (int k = 0; k < NPRED; k++) {
        const float *pa, *pb;
        if (k == 0)      { pa = observed + (size_t)7 * ND; pb = observed + (size_t)6 * ND; }
        else if (k == 1) { pa = pred_out;                  pb = observed + (size_t)7 * ND; }
        else             { pa = pred_out + (size_t)(k-1)*ND; pb = pred_out + (size_t)(k-2)*ND; }
        gemm_tc<<<gemmGrid, 256, GEMM_SMEM>>>(tAh, tAl, tBdh, tBdl, Ah, Al, Bhd, Bld, G);
        gru_update<<<gruGrid, 256>>>(Md, bd, dec_bhh, nullptr, G, pa, pb, h, Ah, Al);
        h2n_pos<<<NB / 8, 256>>>(h, h2n_W, h2n_b, mix_W, mix_b, pa,
                                 rel_out + (size_t)k * NB * 5,
                                 pred_out + (size_t)k * ND);
    }
}